// round 12
// baseline (speedup 1.0000x reference)
#include <cuda_runtime.h>
#include <cuda_fp16.h>
#include <math.h>
#include <cstdint>

#define B_    2
#define S_    2048
#define HID   2048
#define HQ    16
#define HKV   4
#define D_    128
#define MROWS (B_ * S_)      // 4096
#define KVW   (HKV * D_)     // 512

// ---------------- scratch (allocation-free: __device__ globals) ----------------
__device__ float g_qproj[(size_t)MROWS * HID];
__device__ float g_kproj[(size_t)MROWS * KVW];
__device__ float g_vproj[(size_t)MROWS * KVW];
__device__ float g_gate [(size_t)MROWS * HID];

// fp16 operands
__device__ __half g_hs[(size_t)MROWS * HID];
__device__ __half g_wq[(size_t)HID * HID];
__device__ __half g_wk[(size_t)KVW * HID];
__device__ __half g_wv[(size_t)KVW * HID];
__device__ __half g_wg[(size_t)HID * HID];
__device__ __half g_wo[(size_t)HID * HID];
__device__ __half g_at[(size_t)MROWS * HID];

// q/k/v fp16, [b][h][s][d]
__device__ __half g_q[(size_t)B_ * HQ  * S_ * D_];
__device__ __half g_k[(size_t)B_ * HKV * S_ * D_];
__device__ __half g_v[(size_t)B_ * HKV * S_ * D_];

// ---------------- PTX helpers (base sm_100-safe) ----------------
__device__ __forceinline__ uint32_t smem_u32(const void* p) {
    return (uint32_t)__cvta_generic_to_shared(p);
}
#define CP16(dst, src) \
    asm volatile("cp.async.cg.shared.global [%0], [%1], 16;\n" :: "r"(dst), "l"(src))
#define CP_COMMIT() asm volatile("cp.async.commit_group;\n" ::: "memory")
#define CP_WAIT(n)  asm volatile("cp.async.wait_group %0;\n" :: "n"(n) : "memory")

#define LDMX4(r, addr) \
    asm volatile("ldmatrix.sync.aligned.m8n8.x4.shared.b16 {%0,%1,%2,%3}, [%4];" \
        : "=r"((r)[0]), "=r"((r)[1]), "=r"((r)[2]), "=r"((r)[3]) : "r"(addr))
#define LDMX4T(r, addr) \
    asm volatile("ldmatrix.sync.aligned.m8n8.x4.trans.shared.b16 {%0,%1,%2,%3}, [%4];" \
        : "=r"((r)[0]), "=r"((r)[1]), "=r"((r)[2]), "=r"((r)[3]) : "r"(addr))

#define MMAH(d, a, b) \
    asm volatile("mma.sync.aligned.m16n8k16.row.col.f32.f16.f16.f32 " \
        "{%0,%1,%2,%3}, {%4,%5,%6,%7}, {%8,%9}, {%0,%1,%2,%3};" \
        : "+f"((d)[0]), "+f"((d)[1]), "+f"((d)[2]), "+f"((d)[3]) \
        : "r"((a)[0]), "r"((a)[1]), "r"((a)[2]), "r"((a)[3]), "r"((b)[0]), "r"((b)[1]))

__device__ __forceinline__ float fexp2(float x) {
    float y; asm("ex2.approx.ftz.f32 %0, %1;" : "=f"(y) : "f"(x)); return y;
}

// ---------------- convert: fp32 -> fp16 ----------------
__global__ void __launch_bounds__(256) to_half(const float* __restrict__ x,
                                               __half* __restrict__ y, int n)
{
    int i = (blockIdx.x * blockDim.x + threadIdx.x) * 4;
    if (i >= n) return;
    float4 v = *(const float4*)(x + i);
    __half2 h0 = __floats2half2_rn(v.x, v.y);
    __half2 h1 = __floats2half2_rn(v.z, v.w);
    *(__half2*)(y + i)     = h0;
    *(__half2*)(y + i + 2) = h1;
}

// ---------------- fp16 mma.sync GEMM: C[m][n] = sum_k A[m][k]*B[n][k] ----------------
// CTA tile 128x256, 256 threads (8 warps: 2M x 4N, warp tile 64x64), BK=64,
// rows 144B (128 data + 16 pad, conflict-free ldmatrix), cp.async double buffer.
// 1 CTA/SM (110.6 KB smem), halves L2 operand traffic vs 128x128 tiles.
#define BK     64
#define ROWB   144
#define OPBA   (128 * ROWB)         // 18432 (A tile)
#define OPBB   (256 * ROWB)         // 36864 (B tile)
#define STG    (OPBA + OPBB)        // 55296
#define GEMM_SMEM (2 * STG)         // 110592

__device__ __forceinline__ void gemm_body(
    const __half* __restrict__ A, const __half* __restrict__ B,
    float* __restrict__ C, int N, int K, int bm, int bn, char* smem)
{
    const uint32_t sb = smem_u32(smem);
    const int tid  = threadIdx.x;
    const int wid  = tid >> 5, lane = tid & 31;
    const int wm   = wid & 1;          // 2 warps in M: 64 rows each
    const int wn   = wid >> 1;         // 4 warps in N: 64 cols each

    const uint32_t a_off = (uint32_t)((lane & 15) * ROWB + (lane >> 4) * 16);
    const uint32_t b_off = (uint32_t)((lane & 7) * ROWB + ((lane >> 4) & 1) * (8 * ROWB)
                                      + ((lane >> 3) & 1) * 16);

    float acc[4][8][4];
#pragma unroll
    for (int i = 0; i < 4; ++i)
#pragma unroll
        for (int j = 0; j < 8; ++j)
#pragma unroll
            for (int v = 0; v < 4; ++v) acc[i][j][v] = 0.f;

    const int T = K / BK;

    // fill stage s: A 128 rows x 8 chunks (1024), B 256 rows x 8 chunks (2048); 256 threads
#define FILL(s, kt) do {                                                          \
        uint32_t base = sb + (uint32_t)(s) * STG;                                 \
        int k0 = (kt) * BK;                                                       \
        _Pragma("unroll")                                                         \
        for (int c = 0; c < 4; ++c) {                                             \
            int idx = c * 256 + tid;                                              \
            int r = idx >> 3, co = (idx & 7) * 16;                                \
            const char* pa = (const char*)(A + (size_t)(bm + r) * K + k0) + co;   \
            CP16(base + (uint32_t)(r * ROWB + co), pa);                           \
        }                                                                         \
        _Pragma("unroll")                                                         \
        for (int c = 0; c < 8; ++c) {                                             \
            int idx = c * 256 + tid;                                              \
            int r = idx >> 3, co = (idx & 7) * 16;                                \
            const char* pb = (const char*)(B + (size_t)(bn + r) * K + k0) + co;   \
            CP16(base + OPBA + (uint32_t)(r * ROWB + co), pb);                    \
        }                                                                         \
    } while (0)

    FILL(0, 0); CP_COMMIT();

    for (int t = 0; t < T; ++t) {
        const int s = t & 1;
        if (t + 1 < T) { FILL(s ^ 1, t + 1); CP_COMMIT(); CP_WAIT(1); }
        else           { CP_WAIT(0); }
        __syncthreads();

        const uint32_t abase = sb + (uint32_t)s * STG + (uint32_t)(wm * 64) * ROWB;
        const uint32_t bbase = sb + (uint32_t)s * STG + OPBA + (uint32_t)(wn * 64) * ROWB;

#pragma unroll
        for (int ks = 0; ks < 4; ++ks) {       // BK=64 -> 4 k16 steps
            uint32_t af[4][4], bf[4][4];
#pragma unroll
            for (int mi = 0; mi < 4; ++mi)
                LDMX4(af[mi], abase + (uint32_t)(mi * 16) * ROWB + a_off + ks * 32);
#pragma unroll
            for (int p = 0; p < 4; ++p)
                LDMX4(bf[p], bbase + (uint32_t)(p * 16) * ROWB + b_off + ks * 32);
#pragma unroll
            for (int mi = 0; mi < 4; ++mi)
#pragma unroll
                for (int p = 0; p < 4; ++p) {
                    MMAH(acc[mi][2 * p],     af[mi], bf[p]);
                    MMAH(acc[mi][2 * p + 1], af[mi], bf[p] + 2);
                }
        }
        __syncthreads();
    }

    const int r0 = bm + wm * 64 + (lane >> 2);
    const int c0 = bn + wn * 64 + (lane & 3) * 2;
#pragma unroll
    for (int mi = 0; mi < 4; ++mi)
#pragma unroll
        for (int ni = 0; ni < 8; ++ni) {
            int row = r0 + mi * 16;
            int col = c0 + ni * 8;
            *(float2*)(C + (size_t)row * N + col)       = make_float2(acc[mi][ni][0], acc[mi][ni][1]);
            *(float2*)(C + (size_t)(row + 8) * N + col) = make_float2(acc[mi][ni][2], acc[mi][ni][3]);
        }
#undef FILL
}

// fused Q/K/V/G projections: grid.x = 8(Q)+2(K)+2(V)+8(G) = 20, grid.y = 32
__global__ void __launch_bounds__(256, 1) gemm_qkvg()
{
    extern __shared__ char smem[];
    const int bx = blockIdx.x;
    const int bm = blockIdx.y * 128;
    const __half* Bp;
    float* C;
    int N, bn;
    if (bx < 8)       { Bp = g_wq; C = g_qproj; N = HID; bn = bx * 256; }
    else if (bx < 10) { Bp = g_wk; C = g_kproj; N = KVW; bn = (bx - 8) * 256; }
    else if (bx < 12) { Bp = g_wv; C = g_vproj; N = KVW; bn = (bx - 10) * 256; }
    else              { Bp = g_wg; C = g_gate;  N = HID; bn = (bx - 12) * 256; }
    gemm_body(g_hs, Bp, C, N, HID, bm, bn, smem);
}

// generic GEMM (Wo projection): grid (N/256, M/128)
__global__ void __launch_bounds__(256, 1)
gemm_f16(const __half* __restrict__ A, const __half* __restrict__ B,
         float* __restrict__ C, int N, int K)
{
    extern __shared__ char smem[];
    gemm_body(A, B, C, N, K, blockIdx.y * 128, blockIdx.x * 256, smem);
}

// ---------------- fused RMSNorm + RoPE + transpose -> fp16 ----------------
__global__ void __launch_bounds__(256) rope_norm_kernel(const float* __restrict__ cosT,
                                                        const float* __restrict__ sinT,
                                                        const float* __restrict__ qw,
                                                        const float* __restrict__ kw)
{
    const int gw   = (blockIdx.x * blockDim.x + threadIdx.x) >> 5;
    const int lane = threadIdx.x & 31;
    const int NQ = MROWS * HQ;
    const int NK = MROWS * HKV;

    if (gw < NQ + NK) {
        bool isq = (gw < NQ);
        int idx = isq ? gw : gw - NQ;
        int nh  = isq ? HQ : HKV;
        int h = idx % nh;
        int m = idx / nh;
        int s = m % S_, b = m / S_;
        const float* x = (isq ? g_qproj + (size_t)m * HID : g_kproj + (size_t)m * KVW) + h * D_;
        const float* w = isq ? qw : kw;

        float x0 = x[lane], x1 = x[lane + 32], x2 = x[lane + 64], x3 = x[lane + 96];
        float ss = x0 * x0 + x1 * x1 + x2 * x2 + x3 * x3;
#pragma unroll
        for (int off = 16; off; off >>= 1) ss += __shfl_xor_sync(0xffffffffu, ss, off);
        float r = rsqrtf(ss * (1.f / 128.f) + 1e-6f);
        x0 = x0 * r * w[lane];
        x1 = x1 * r * w[lane + 32];
        x2 = x2 * r * w[lane + 64];
        x3 = x3 * r * w[lane + 96];

        const float* c  = cosT + (size_t)s * D_;
        const float* sn = sinT + (size_t)s * D_;
        float o0 = x0 * c[lane]      - x2 * sn[lane];
        float o1 = x1 * c[lane + 32] - x3 * sn[lane + 32];
        float o2 = x2 * c[lane + 64] + x0 * sn[lane + 64];
        float o3 = x3 * c[lane + 96] + x1 * sn[lane + 96];

        size_t base = isq ? (size_t)((b * HQ + h) * S_ + s) * D_
                          : (size_t)((b * HKV + h) * S_ + s) * D_;
        __half* o = (isq ? g_q : g_k) + base;
        o[lane]      = __float2half_rn(o0);
        o[lane + 32] = __float2half_rn(o1);
        o[lane + 64] = __float2half_rn(o2);
        o[lane + 96] = __float2half_rn(o3);
    } else if (gw < NQ + 2 * NK) {
        int vi = gw - NQ - NK;
        int h = vi % HKV;
        int m = vi / HKV;
        int s = m % S_, b = m / S_;
        const float* x = g_vproj + (size_t)m * KVW + h * D_;
        __half* o = g_v + (size_t)((b * HKV + h) * S_ + s) * D_;
        o[lane]      = __float2half_rn(x[lane]);
        o[lane + 32] = __float2half_rn(x[lane + 32]);
        o[lane + 64] = __float2half_rn(x[lane + 64]);
        o[lane + 96] = __float2half_rn(x[lane + 96]);
    }
}

// ---------------- tensor-core flash attention (causal, fp16) ----------------
// CTA: 128 q-rows x 64-wide KV tiles, 8 warps. Row stride 272B (17x16B, conflict-free).
#define QR    128
#define KT    64
#define DSTR  272
#define QARR  (QR * DSTR)        // 34816
#define KARR  (KT * DSTR)        // 17408
#define KVSTG (2 * KARR)         // 34816 (K, V)
#define ATTN_SMEM (QARR + 2 * KVSTG)   // 104448

__global__ void __launch_bounds__(256) attn_tc(const float* __restrict__ gate)
{
    extern __shared__ char smc[];
    const uint32_t sb = smem_u32(smc);
    const int tid = threadIdx.x;
    const int wid = tid >> 5, lane = tid & 31;
    const int bh = blockIdx.y;
    const int b = bh >> 4, h = bh & 15;
    const int kvh = h >> 2;
    const int qt = gridDim.x - 1 - blockIdx.x;   // heavy tiles first
    const int q0 = qt * QR;

    const char* Q_g = (const char*)(g_q + ((size_t)(b * HQ + h) * S_ + q0) * D_);
    const char* K_g = (const char*)(g_k + (size_t)(b * HKV + kvh) * S_ * D_);
    const char* V_g = (const char*)(g_v + (size_t)(b * HKV + kvh) * S_ * D_);

    const int T = q0 / KT + 2;

#define KVFILL(s, t) do {                                                   \
        uint32_t base = sb + QARR + (uint32_t)(s) * KVSTG;                  \
        size_t gk = (size_t)(t) * KT * 256;                                 \
        _Pragma("unroll")                                                   \
        for (int c = 0; c < 4; ++c) {                                       \
            int idx = c * 256 + tid;                                        \
            int r = idx >> 4, o16 = (idx & 15) * 16;                        \
            uint32_t so = (uint32_t)(r * DSTR + o16);                       \
            size_t gb = gk + (size_t)r * 256 + o16;                         \
            CP16(base + so,        K_g + gb);                               \
            CP16(base + KARR + so, V_g + gb);                               \
        }                                                                   \
    } while (0)

    {
#pragma unroll
        for (int c = 0; c < 8; ++c) {
            int idx = c * 256 + tid;
            int r = idx >> 4, o16 = (idx & 15) * 16;
            uint32_t so = (uint32_t)(r * DSTR + o16);
            CP16(sb + so, Q_g + (size_t)r * 256 + o16);
        }
        KVFILL(0, 0); CP_COMMIT();
        KVFILL(1, 1); CP_COMMIT();
    }

    const uint32_t a_off = (uint32_t)((lane & 15) * DSTR + (lane >> 4) * 16);
    const uint32_t b_off = (uint32_t)((lane & 7) * DSTR + ((lane >> 4) & 1) * (8 * DSTR)
                                      + ((lane >> 3) & 1) * 16);
    const uint32_t qbase = sb + (uint32_t)(wid * 16) * DSTR;

    float o[16][4];
#pragma unroll
    for (int j = 0; j < 16; ++j)
#pragma unroll
        for (int v = 0; v < 4; ++v) o[j][v] = 0.f;
    float mi[2] = {-1e30f, -1e30f};
    float li[2] = {0.f, 0.f};

    const float SC = 0.08838834764831845f * 1.4426950408889634f;  // scale * log2(e)

    for (int t = 0; t < T; ++t) {
        const int s = t & 1;
        if (t + 1 < T) CP_WAIT(1); else CP_WAIT(0);
        __syncthreads();

        const uint32_t kbase = sb + QARR + (uint32_t)s * KVSTG;
        const uint32_t vbase = kbase + KARR;

        // ---- S = Q K^T ----
        float sc[8][4];
#pragma unroll
        for (int j = 0; j < 8; ++j)
#pragma unroll
            for (int v = 0; v < 4; ++v) sc[j][v] = 0.f;

#pragma unroll
        for (int kk = 0; kk < 8; ++kk) {
            uint32_t ah[4], kf[4][4];
            LDMX4(ah, qbase + a_off + kk * 32);
#pragma unroll
            for (int p = 0; p < 4; ++p)
                LDMX4(kf[p], kbase + (uint32_t)(p * 16) * DSTR + b_off + kk * 32);
#pragma unroll
            for (int p = 0; p < 4; ++p) {
                MMAH(sc[2 * p],     ah, kf[p]);
                MMAH(sc[2 * p + 1], ah, kf[p] + 2);
            }
        }

        const int k0 = t * KT;
        const bool tail = (t + 2 >= T);
#pragma unroll
        for (int tl = 0; tl < 8; ++tl)
#pragma unroll
            for (int v = 0; v < 4; ++v) {
                float x = sc[tl][v] * SC;
                if (tail) {
                    int col = k0 + tl * 8 + (lane & 3) * 2 + (v & 1);
                    int row = q0 + wid * 16 + (lane >> 2) + ((v >> 1) << 3);
                    if (col > row) x = -1e30f;
                }
                sc[tl][v] = x;
            }

        // ---- online softmax; pack P to fp16 fragments ----
        uint32_t PH0[8], PH1[8];
#pragma unroll
        for (int hh = 0; hh < 2; ++hh) {
            float rm = -1e30f;
#pragma unroll
            for (int tl = 0; tl < 8; ++tl)
                rm = fmaxf(rm, fmaxf(sc[tl][2 * hh], sc[tl][2 * hh + 1]));
            rm = fmaxf(rm, __shfl_xor_sync(0xffffffffu, rm, 1));
            rm = fmaxf(rm, __shfl_xor_sync(0xffffffffu, rm, 2));
            float mnew = fmaxf(mi[hh], rm);
            float corr = fexp2(mi[hh] - mnew);
            float rs = 0.f;
#pragma unroll
            for (int tl = 0; tl < 8; ++tl) {
                float p0 = fexp2(sc[tl][2 * hh]     - mnew);
                float p1 = fexp2(sc[tl][2 * hh + 1] - mnew);
                rs += p0 + p1;
                __half2 hp = __floats2half2_rn(p0, p1);
                if (hh == 0) PH0[tl] = *(uint32_t*)&hp;
                else         PH1[tl] = *(uint32_t*)&hp;
            }
            rs += __shfl_xor_sync(0xffffffffu, rs, 1);
            rs += __shfl_xor_sync(0xffffffffu, rs, 2);
            li[hh] = li[hh] * corr + rs;
            mi[hh] = mnew;
#pragma unroll
            for (int j = 0; j < 16; ++j) {
                o[j][2 * hh]     *= corr;
                o[j][2 * hh + 1] *= corr;
            }
        }

        // ---- O += P V (P fragments from registers, V via ldmatrix.trans) ----
#pragma unroll
        for (int kk2 = 0; kk2 < 4; ++kk2) {
            uint32_t ph[4] = {PH0[2 * kk2], PH1[2 * kk2], PH0[2 * kk2 + 1], PH1[2 * kk2 + 1]};
#pragma unroll
            for (int half = 0; half < 2; ++half) {
                uint32_t vf[4][4];
#pragma unroll
                for (int p = 0; p < 4; ++p)
                    LDMX4T(vf[p], vbase + (uint32_t)(kk2 * 16) * DSTR + a_off
                                  + (half * 4 + p) * 32);
#pragma unroll
                for (int p = 0; p < 4; ++p) {
                    int q = half * 4 + p;
                    MMAH(o[2 * q],     ph, vf[p]);
                    MMAH(o[2 * q + 1], ph, vf[p] + 2);
                }
            }
        }

        __syncthreads();
        if (t + 2 < T) { KVFILL(s, t + 2); CP_COMMIT(); }
    }

    // ---- epilogue: normalize, sigmoid-gate, fp16 store ----
#pragma unroll
    for (int hh = 0; hh < 2; ++hh) {
        int row = q0 + wid * 16 + (lane >> 2) + hh * 8;
        size_t m = (size_t)b * S_ + row;
        float inv = 1.f / li[hh];
        const float* gr = gate + m * HID + h * D_;
        __half* oa = g_at + m * HID + h * D_;
#pragma unroll
        for (int j = 0; j < 16; ++j) {
            int d0 = j * 8 + (lane & 3) * 2;
            float2 gv = *(const float2*)(gr + d0);
            float s0 = 1.f / (1.f + fexp2(-gv.x * 1.4426950408889634f));
            float s1 = 1.f / (1.f + fexp2(-gv.y * 1.4426950408889634f));
            float v0 = o[j][2 * hh]     * inv * s0;
            float v1 = o[j][2 * hh + 1] * inv * s1;
            *(__half2*)(oa + d0) = __floats2half2_rn(v0, v1);
        }
    }
#undef KVFILL
}

// ---------------- launch ----------------
extern "C" void kernel_launch(void* const* d_in, const int* in_sizes, int n_in,
                              void* d_out, int out_size)
{
    const float* hs   = (const float*)d_in[0];
    const float* cosT = (const float*)d_in[1];
    const float* sinT = (const float*)d_in[2];
    const float* Wq   = (const float*)d_in[3];
    const float* Wk   = (const float*)d_in[4];
    const float* Wv   = (const float*)d_in[5];
    const float* Wg   = (const float*)d_in[6];
    const float* Wo   = (const float*)d_in[7];
    const float* qw   = (const float*)d_in[8];
    const float* kw   = (const float*)d_in[9];
    float* out = (float*)d_out;

    float* gp;
    cudaGetSymbolAddress((void**)&gp, g_gate);

    __half *hsh, *wqh, *wkh, *wvh, *wgh, *woh, *ath;
    cudaGetSymbolAddress((void**)&hsh, g_hs);
    cudaGetSymbolAddress((void**)&wqh, g_wq);
    cudaGetSymbolAddress((void**)&wkh, g_wk);
    cudaGetSymbolAddress((void**)&wvh, g_wv);
    cudaGetSymbolAddress((void**)&wgh, g_wg);
    cudaGetSymbolAddress((void**)&woh, g_wo);
    cudaGetSymbolAddress((void**)&ath, g_at);

    cudaFuncSetAttribute(gemm_qkvg, cudaFuncAttributeMaxDynamicSharedMemorySize, GEMM_SMEM);
    cudaFuncSetAttribute(gemm_f16,  cudaFuncAttributeMaxDynamicSharedMemorySize, GEMM_SMEM);
    cudaFuncSetAttribute(attn_tc,   cudaFuncAttributeMaxDynamicSharedMemorySize, ATTN_SMEM);

    // fp32 -> fp16 converts
    const int nHS = MROWS * HID, nSq = HID * HID, nKv = KVW * HID;
    to_half<<<nHS / 1024, 256>>>(hs, hsh, nHS);
    to_half<<<nSq / 1024, 256>>>(Wq, wqh, nSq);
    to_half<<<nKv / 1024, 256>>>(Wk, wkh, nKv);
    to_half<<<nKv / 1024, 256>>>(Wv, wvh, nKv);
    to_half<<<nSq / 1024, 256>>>(Wg, wgh, nSq);
    to_half<<<nSq / 1024, 256>>>(Wo, woh, nSq);

    // fused Q/K/V/G projections (fp16 tensor cores, 128x256 CTA tiles)
    gemm_qkvg<<<dim3(20, MROWS / 128), 256, GEMM_SMEM>>>();

    // RMSNorm + RoPE + transpose -> fp16 q/k/v
    {
        int total_warps = MROWS * (HQ + 2 * HKV);
        rope_norm_kernel<<<total_warps / 8, 256>>>(cosT, sinT, qw, kw);
    }

    // tensor-core causal flash attention + gated epilogue
    attn_tc<<<dim3(S_ / QR, B_ * HQ), 256, ATTN_SMEM>>>(gp);

    // output projection
    gemm_f16<<<dim3(HID / 256, MROWS / 128), 256, GEMM_SMEM>>>(ath, woh, out, HID, HID);
}